// round 13
// baseline (speedup 1.0000x reference)
#include <cuda_runtime.h>
#include <cuda_fp16.h>
#include <cstdint>

// ---------------------------------------------------------------------------
// MaskMultiheadAttention  (B=4, N=2048, C=256, H=8, Dh=32)
// out = (query + proj_o(attn_masked @ V), softmax(QK^T*scale))
// d_out layout: [out_query (B*N*C floats)] [attn_vis (B*H*N*N floats)]
// Attention: QK^T via mma.sync tf32, probs stored fp16, PV via mma.sync fp16.
// 256-thread CTAs, ~103KB smem -> 2 CTAs/SM for phase overlap.
// ---------------------------------------------------------------------------

constexpr int B_ = 4, N_ = 2048, C_ = 256, H_ = 8, D_ = 32;
constexpr float SCALE_L2 = 0.17677669529663687f * 1.4426950408889634f;

__device__ float  g_q [B_ * N_ * C_];
__device__ float  g_k [B_ * N_ * C_];
__device__ float  g_v [B_ * N_ * C_];
__device__ float  g_x [B_ * N_ * C_];
__device__ __half g_mt[(size_t)B_ * N_ * N_];   // mask^T/colmax (fp16)
__device__ int    g_cmax[B_ * N_];

#define DEV_INLINE __device__ __forceinline__
typedef unsigned long long ull;

DEV_INLINE ull pk2(float lo, float hi) {
    ull r; asm("mov.b64 %0, {%1, %2};" : "=l"(r) : "f"(lo), "f"(hi)); return r;
}
DEV_INLINE float2 upk2(ull v) {
    float2 f; asm("mov.b64 {%0, %1}, %2;" : "=f"(f.x), "=f"(f.y) : "l"(v)); return f;
}
DEV_INLINE ull ffma2(ull a, ull b, ull c) {
    ull d; asm("fma.rn.f32x2 %0, %1, %2, %3;" : "=l"(d) : "l"(a), "l"(b), "l"(c)); return d;
}
DEV_INLINE float ex2f(float x) {
    float y; asm("ex2.approx.ftz.f32 %0, %1;" : "=f"(y) : "f"(x)); return y;
}
DEV_INLINE uint32_t fb(float x) { return __float_as_uint(x); }

// m16n8k8 tf32 (QK^T). Lane map (g=lane>>2, tq=lane&3):
//  A: a0=(g,tq) a1=(g+8,tq) a2=(g,tq+4) a3=(g+8,tq+4)
//  B: b0=(k=tq,n=g) b1=(k=tq+4,n=g)
//  D: d0=(g,2tq) d1=(g,2tq+1) d2=(g+8,2tq) d3=(g+8,2tq+1)
DEV_INLINE void mma8(float4& d, uint32_t a0, uint32_t a1, uint32_t a2, uint32_t a3,
                     uint32_t b0, uint32_t b1) {
    asm volatile("mma.sync.aligned.m16n8k8.row.col.f32.tf32.tf32.f32 "
                 "{%0,%1,%2,%3}, {%4,%5,%6,%7}, {%8,%9}, {%0,%1,%2,%3};"
                 : "+f"(d.x), "+f"(d.y), "+f"(d.z), "+f"(d.w)
                 : "r"(a0), "r"(a1), "r"(a2), "r"(a3), "r"(b0), "r"(b1));
}
// m16n8k16 fp16 (PV). A: a0=(g,2tq..+1) a1=(g+8,..) a2=(g,2tq+8..) a3=(g+8,..)
//  B: b0=(k=2tq..+1,n=g) b1=(k=2tq+8..+9,n=g).  D as above.
DEV_INLINE void mma16h(float4& d, uint32_t a0, uint32_t a1, uint32_t a2, uint32_t a3,
                       uint32_t b0, uint32_t b1) {
    asm volatile("mma.sync.aligned.m16n8k16.row.col.f32.f16.f16.f32 "
                 "{%0,%1,%2,%3}, {%4,%5,%6,%7}, {%8,%9}, {%0,%1,%2,%3};"
                 : "+f"(d.x), "+f"(d.y), "+f"(d.z), "+f"(d.w)
                 : "r"(a0), "r"(a1), "r"(a2), "r"(a3), "r"(b0), "r"(b1));
}

// ---------------------------------------------------------------------------
// QKV GEMM (NT, fused 3 outputs) — FFMA2 (proven)
// ---------------------------------------------------------------------------
__global__ void __launch_bounds__(256) gemm_qkv(
    const float* __restrict__ A,
    const float* __restrict__ W0, const float* __restrict__ b0, float* __restrict__ o0,
    const float* __restrict__ W1, const float* __restrict__ b1, float* __restrict__ o1,
    const float* __restrict__ W2, const float* __restrict__ b2, float* __restrict__ o2) {
    __shared__ float As[2][16][64];
    __shared__ float Bs[2][3][16][64];
    const int t  = threadIdx.x;
    const int m0 = blockIdx.y * 64;
    const int n0 = blockIdx.x * 64;
    const int ty = t >> 4, tx = t & 15;
    const int lr = t >> 2;
    const int lk = (t & 3) * 4;

    const float4* Ap  = (const float4*)&A [(size_t)(m0 + lr) * C_ + lk];
    const float4* W0p = (const float4*)&W0[(size_t)(n0 + lr) * C_ + lk];
    const float4* W1p = (const float4*)&W1[(size_t)(n0 + lr) * C_ + lk];
    const float4* W2p = (const float4*)&W2[(size_t)(n0 + lr) * C_ + lk];

    float4 sa = Ap[0], s0 = W0p[0], s1 = W1p[0], s2 = W2p[0];
    {
        As[0][lk+0][lr]=sa.x; As[0][lk+1][lr]=sa.y; As[0][lk+2][lr]=sa.z; As[0][lk+3][lr]=sa.w;
        Bs[0][0][lk+0][lr]=s0.x; Bs[0][0][lk+1][lr]=s0.y; Bs[0][0][lk+2][lr]=s0.z; Bs[0][0][lk+3][lr]=s0.w;
        Bs[0][1][lk+0][lr]=s1.x; Bs[0][1][lk+1][lr]=s1.y; Bs[0][1][lk+2][lr]=s1.z; Bs[0][1][lk+3][lr]=s1.w;
        Bs[0][2][lk+0][lr]=s2.x; Bs[0][2][lk+1][lr]=s2.y; Bs[0][2][lk+2][lr]=s2.z; Bs[0][2][lk+3][lr]=s2.w;
    }
    __syncthreads();

    ull acc[3][4][2];
#pragma unroll
    for (int w = 0; w < 3; w++)
#pragma unroll
        for (int i = 0; i < 4; i++) { acc[w][i][0] = 0ull; acc[w][i][1] = 0ull; }

    for (int kt = 0; kt < 16; kt++) {
        const int cur = kt & 1;
        if (kt < 15) {
            sa = Ap[4*(kt+1)]; s0 = W0p[4*(kt+1)]; s1 = W1p[4*(kt+1)]; s2 = W2p[4*(kt+1)];
        }
#pragma unroll
        for (int kk = 0; kk < 16; kk++) {
            ull bv[3][2];
#pragma unroll
            for (int w = 0; w < 3; w++) {
                bv[w][0] = *(const ull*)&Bs[cur][w][kk][tx*4];
                bv[w][1] = *(const ull*)&Bs[cur][w][kk][tx*4+2];
            }
#pragma unroll
            for (int i = 0; i < 4; i++) {
                float a = As[cur][kk][ty*4+i];
                ull ad = pk2(a, a);
#pragma unroll
                for (int w = 0; w < 3; w++) {
                    acc[w][i][0] = ffma2(ad, bv[w][0], acc[w][i][0]);
                    acc[w][i][1] = ffma2(ad, bv[w][1], acc[w][i][1]);
                }
            }
        }
        if (kt < 15) {
            const int nb = cur ^ 1;
            As[nb][lk+0][lr]=sa.x; As[nb][lk+1][lr]=sa.y; As[nb][lk+2][lr]=sa.z; As[nb][lk+3][lr]=sa.w;
            Bs[nb][0][lk+0][lr]=s0.x; Bs[nb][0][lk+1][lr]=s0.y; Bs[nb][0][lk+2][lr]=s0.z; Bs[nb][0][lk+3][lr]=s0.w;
            Bs[nb][1][lk+0][lr]=s1.x; Bs[nb][1][lk+1][lr]=s1.y; Bs[nb][1][lk+2][lr]=s1.z; Bs[nb][1][lk+3][lr]=s1.w;
            Bs[nb][2][lk+0][lr]=s2.x; Bs[nb][2][lk+1][lr]=s2.y; Bs[nb][2][lk+2][lr]=s2.z; Bs[nb][2][lk+3][lr]=s2.w;
        }
        __syncthreads();
    }

    const float* bias[3] = {b0, b1, b2};
    float*       outp[3] = {o0, o1, o2};
#pragma unroll
    for (int w = 0; w < 3; w++)
#pragma unroll
        for (int i = 0; i < 4; i++) {
            int m = m0 + ty*4 + i;
#pragma unroll
            for (int p = 0; p < 2; p++) {
                int n = n0 + tx*4 + p*2;
                float2 v = upk2(acc[w][i][p]);
                v.x += bias[w][n]; v.y += bias[w][n+1];
                *(float2*)&outp[w][(size_t)m * C_ + n] = v;
            }
        }
}

// ---------------------------------------------------------------------------
// Output GEMM with bias + residual — FFMA2 (proven)
// ---------------------------------------------------------------------------
__global__ void __launch_bounds__(256) gemm_o(const float* __restrict__ A,
                                              const float* __restrict__ W,
                                              const float* __restrict__ bias,
                                              const float* __restrict__ res,
                                              float* __restrict__ out) {
    __shared__ float As[2][16][64];
    __shared__ float Bs[2][16][64];
    const int t  = threadIdx.x;
    const int m0 = blockIdx.y * 64;
    const int n0 = blockIdx.x * 64;
    const int ty = t >> 4, tx = t & 15;
    const int lr = t >> 2;
    const int lk = (t & 3) * 4;

    const float4* Ap = (const float4*)&A[(size_t)(m0 + lr) * C_ + lk];
    const float4* Wp = (const float4*)&W[(size_t)(n0 + lr) * C_ + lk];

    float4 sa = Ap[0], sw = Wp[0];
    As[0][lk+0][lr]=sa.x; As[0][lk+1][lr]=sa.y; As[0][lk+2][lr]=sa.z; As[0][lk+3][lr]=sa.w;
    Bs[0][lk+0][lr]=sw.x; Bs[0][lk+1][lr]=sw.y; Bs[0][lk+2][lr]=sw.z; Bs[0][lk+3][lr]=sw.w;
    __syncthreads();

    ull acc[4][2];
#pragma unroll
    for (int i = 0; i < 4; i++) { acc[i][0] = 0ull; acc[i][1] = 0ull; }

    for (int kt = 0; kt < 16; kt++) {
        const int cur = kt & 1;
        if (kt < 15) { sa = Ap[4*(kt+1)]; sw = Wp[4*(kt+1)]; }
#pragma unroll
        for (int kk = 0; kk < 16; kk++) {
            ull bv0 = *(const ull*)&Bs[cur][kk][tx*4];
            ull bv1 = *(const ull*)&Bs[cur][kk][tx*4+2];
#pragma unroll
            for (int i = 0; i < 4; i++) {
                float a = As[cur][kk][ty*4+i];
                ull ad = pk2(a, a);
                acc[i][0] = ffma2(ad, bv0, acc[i][0]);
                acc[i][1] = ffma2(ad, bv1, acc[i][1]);
            }
        }
        if (kt < 15) {
            const int nb = cur ^ 1;
            As[nb][lk+0][lr]=sa.x; As[nb][lk+1][lr]=sa.y; As[nb][lk+2][lr]=sa.z; As[nb][lk+3][lr]=sa.w;
            Bs[nb][lk+0][lr]=sw.x; Bs[nb][lk+1][lr]=sw.y; Bs[nb][lk+2][lr]=sw.z; Bs[nb][lk+3][lr]=sw.w;
        }
        __syncthreads();
    }
#pragma unroll
    for (int i = 0; i < 4; i++) {
        int m = m0 + ty*4 + i;
#pragma unroll
        for (int p = 0; p < 2; p++) {
            int n = n0 + tx*4 + p*2;
            float2 v = upk2(acc[i][p]);
            v.x += bias[n]   + res[(size_t)m * C_ + n];
            v.y += bias[n+1] + res[(size_t)m * C_ + n + 1];
            *(float2*)&out[(size_t)m * C_ + n] = v;
        }
    }
}

// ---------------------------------------------------------------------------
// mask: column max, then normalized transpose (fp16): g_mt[b][q][k]
// ---------------------------------------------------------------------------
__global__ void __launch_bounds__(256) cmax_init() {
    int i = blockIdx.x * 256 + threadIdx.x;
    if (i < B_ * N_) g_cmax[i] = 0;
}
__global__ void __launch_bounds__(256) cmax_k(const float* __restrict__ mask) {
    int q = blockIdx.x * 256 + threadIdx.x;
    int b = blockIdx.z;
    const float* p = mask + (size_t)b * N_ * N_ + (size_t)(blockIdx.y * 256) * N_ + q;
    float m = 0.f;
#pragma unroll 8
    for (int k = 0; k < 256; k++) m = fmaxf(m, p[(size_t)k * N_]);
    atomicMax(&g_cmax[b * N_ + q], __float_as_int(m));
}
__global__ void __launch_bounds__(256) mt_k(const float* __restrict__ mask) {
    __shared__ float tl[64][65];
    const int t  = threadIdx.x;
    const int k0 = blockIdx.x * 64, qq0 = blockIdx.y * 64, b = blockIdx.z;
#pragma unroll
    for (int i = 0; i < 16; i++) {
        int idx = t + 256 * i;
        int r = idx >> 6, c = idx & 63;
        tl[r][c] = mask[((size_t)(b * N_ + k0 + r)) * N_ + qq0 + c];
    }
    __syncthreads();
#pragma unroll
    for (int i = 0; i < 16; i++) {
        int idx = t + 256 * i;
        int r = idx >> 6, c = idx & 63;
        float ic = 1.0f / __int_as_float(g_cmax[b * N_ + qq0 + r]);
        g_mt[((size_t)(b * N_ + qq0 + r)) * N_ + k0 + c] = __float2half(tl[c][r] * ic);
    }
}

// ---------------------------------------------------------------------------
// fused attention: one CTA = (b, h, 16 q rows). 256 threads (8 warps),
// ~103KB smem -> 2 CTAs/SM. QK^T tf32, probs fp16, PV fp16.
// ---------------------------------------------------------------------------
constexpr int PSH    = 2056;              // probs row stride (halves)
constexpr int PSH32  = PSH / 2;           // 1028 (b32 units)
constexpr int KTW    = 256;               // keys per tile
constexpr int KVS    = 36;                // K smem row stride (fp32)
constexpr int VTS    = 266;               // V^T smem row stride (halves)
constexpr int QFS    = 36;                // q smem row stride
constexpr int XSTR   = 36;                // x staging row stride
constexpr int XWARP  = 576;               // per-warp x staging (16*36)
constexpr int OFF_KV = 16448;             // probs: 16*2056 halves = 16448 floats
constexpr int KVSZ   = KTW * KVS;         // 9216 floats (>= V^T 32*266/2=4256, >= 8*576)
constexpr int OFF_QF = OFF_KV + KVSZ;     // 25664
constexpr int OFF_ST = OFF_QF + 16*QFS;   // 26240
constexpr int SM_FLOATS = OFF_ST + 16 + 128;  // invs16 + wpart128 = 26384
constexpr int SM_BYTES  = SM_FLOATS * 4;      // 105536 B

__global__ void __launch_bounds__(256, 2) attn_k(float* __restrict__ attn_out) {
    extern __shared__ float sm[];
    __half*   probs_h  = (__half*)sm;
    uint32_t* probs_32 = (uint32_t*)sm;
    float*    kvf      = sm + OFF_KV;
    __half*   vsmh     = (__half*)kvf;
    uint32_t* vsm32    = (uint32_t*)kvf;
    float*    qf       = sm + OFF_QF;
    float*    invs     = sm + OFF_ST;       // [16]
    float*    wpart    = invs + 16;         // [8 warps][16 rows]

    const int t    = threadIdx.x;
    const int wid  = t >> 5, lane = t & 31;
    const int g    = lane >> 2, tq = lane & 3;
    const int q0   = blockIdx.x * 16;
    const int h    = blockIdx.y;
    const int b    = blockIdx.z;

    const float* qsrc = g_q + ((size_t)b * N_ + q0) * C_ + h * D_;
    const float* ksrc = g_k + (size_t)b * N_ * C_ + h * D_;
    const float* vsrc = g_v + (size_t)b * N_ * C_ + h * D_;

    // ---- q tile: q*scale, stride 36 ----
#pragma unroll
    for (int i = 0; i < 2; i++) {
        int idx = t + 256 * i;
        int qi = idx >> 5, d = idx & 31;
        qf[qi * QFS + d] = qsrc[(size_t)qi * C_ + d] * SCALE_L2;
    }

    float4 st[8];
    // prologue: K tile 0 (coalesced: 8 lanes per token row)
#pragma unroll
    for (int i = 0; i < 8; i++) {
        int idx = t + 256 * i, kk = idx >> 3, j = idx & 7;
        st[i] = *(const float4*)&ksrc[(size_t)kk * C_ + j * 4];
    }
    __syncthreads();   // qf visible
#pragma unroll
    for (int i = 0; i < 8; i++) {
        int idx = t + 256 * i, kk = idx >> 3, j = idx & 7;
        *(float4*)&kvf[kk * KVS + j * 4] = st[i];
    }
    __syncthreads();

    // ---- Q A-fragments (invariant) : 16 regs ----
    uint32_t qa[4][4];
#pragma unroll
    for (int kc = 0; kc < 4; kc++) {
        qa[kc][0] = fb(qf[ g      * QFS + 8*kc + tq]);
        qa[kc][1] = fb(qf[(g + 8) * QFS + 8*kc + tq]);
        qa[kc][2] = fb(qf[ g      * QFS + 8*kc + tq + 4]);
        qa[kc][3] = fb(qf[(g + 8) * QFS + 8*kc + tq + 4]);
    }

    // ---- P1: S = QK^T (tf32 mma), exp2 + fp32 rowsum, store e as fp16 ----
    const int nb = wid * 32;
    float rs_lo = 0.f, rs_hi = 0.f;
    for (int kt = 0; kt < 8; kt++) {
        if (kt < 7) {
            const int k0n = (kt + 1) * KTW;
#pragma unroll
            for (int i = 0; i < 8; i++) {
                int idx = t + 256 * i, kk = idx >> 3, j = idx & 7;
                st[i] = *(const float4*)&ksrc[(size_t)(k0n + kk) * C_ + j * 4];
            }
        }
        float4 acc[4];
#pragma unroll
        for (int nt = 0; nt < 4; nt++) acc[nt] = make_float4(0.f, 0.f, 0.f, 0.f);
#pragma unroll
        for (int kc = 0; kc < 4; kc++) {
#pragma unroll
            for (int nt = 0; nt < 4; nt++) {
                const int tok = nb + 8*nt + g;
                uint32_t b0 = fb(kvf[tok * KVS + 8*kc + tq]);
                uint32_t b1 = fb(kvf[tok * KVS + 8*kc + tq + 4]);
                mma8(acc[nt], qa[kc][0], qa[kc][1], qa[kc][2], qa[kc][3], b0, b1);
            }
        }
        const int k0 = kt * KTW;
#pragma unroll
        for (int nt = 0; nt < 4; nt++) {
            float e0 = ex2f(acc[nt].x), e1 = ex2f(acc[nt].y);
            float e2 = ex2f(acc[nt].z), e3 = ex2f(acc[nt].w);
            rs_lo += e0 + e1; rs_hi += e2 + e3;
            int col = k0 + nb + 8*nt + 2*tq;
            *(__half2*)&probs_h[(size_t) g      * PSH + col] = __floats2half2_rn(e0, e1);
            *(__half2*)&probs_h[(size_t)(g + 8) * PSH + col] = __floats2half2_rn(e2, e3);
        }
        __syncthreads();
        if (kt < 7) {
#pragma unroll
            for (int i = 0; i < 8; i++) {
                int idx = t + 256 * i, kk = idx >> 3, j = idx & 7;
                *(float4*)&kvf[kk * KVS + j * 4] = st[i];
            }
            __syncthreads();
        }
    }

    // rowsum: quad reduce then cross-warp combine
    rs_lo += __shfl_xor_sync(0xffffffffu, rs_lo, 1);
    rs_lo += __shfl_xor_sync(0xffffffffu, rs_lo, 2);
    rs_hi += __shfl_xor_sync(0xffffffffu, rs_hi, 1);
    rs_hi += __shfl_xor_sync(0xffffffffu, rs_hi, 2);
    if (tq == 0) {
        wpart[wid * 16 + g]     = rs_lo;
        wpart[wid * 16 + g + 8] = rs_hi;
    }
    // stage V tile 0 (hidden behind stats + P3)
#pragma unroll
    for (int i = 0; i < 8; i++) {
        int idx = t + 256 * i, kk = idx >> 3, j = idx & 7;
        st[i] = *(const float4*)&vsrc[(size_t)kk * C_ + j * 4];
    }
    __syncthreads();
    if (t < 16) {
        float s = 0.f;
#pragma unroll
        for (int w = 0; w < 8; w++) s += wpart[w * 16 + t];
        invs[t] = 1.0f / s;
    }
    __syncthreads();
    // store V^T tile 0 as fp16: vsmh[d][tok], stride 266 (kvf free after P1)
#pragma unroll
    for (int i = 0; i < 8; i++) {
        int idx = t + 256 * i, kk = idx >> 3, j = idx & 7;
        vsmh[(4*j + 0) * VTS + kk] = __float2half(st[i].x);
        vsmh[(4*j + 1) * VTS + kk] = __float2half(st[i].y);
        vsmh[(4*j + 2) * VTS + kk] = __float2half(st[i].z);
        vsmh[(4*j + 3) * VTS + kk] = __float2half(st[i].w);
    }

    // ---- P3 merged: vis = e*invs (streaming) ; probs = half(vis * g_mt) ----
    {
        float4* ao4 = (float4*)(attn_out + (((size_t)b * H_ + h) * N_ + q0) * N_);
        const uint2* mt2 = (const uint2*)(g_mt + ((size_t)b * N_ + q0) * N_);
        uint2* p2 = (uint2*)probs_h;
#pragma unroll 4
        for (int i = 0; i < 32; i++) {
            int idx = t + 256 * i;
            int qi = idx >> 9, m = idx & 511;           // 512 uint2 (4 halves) per row
            uint2 pv = p2[(size_t)qi * (PSH/4) + m];
            float2 f01 = __half22float2(*(__half2*)&pv.x);
            float2 f23 = __half22float2(*(__half2*)&pv.y);
            float s = invs[qi];
            float4 v = make_float4(f01.x * s, f01.y * s, f23.x * s, f23.y * s);
            __stcs(&ao4[(size_t)qi * 512 + m], v);
            uint2 mv = mt2[(size_t)qi * 512 + m];
            float2 m01 = __half22float2(*(__half2*)&mv.x);
            float2 m23 = __half22float2(*(__half2*)&mv.y);
            uint2 outp;
            *(__half2*)&outp.x = __floats2half2_rn(v.x * m01.x, v.y * m01.y);
            *(__half2*)&outp.y = __floats2half2_rn(v.z * m23.x, v.w * m23.y);
            p2[(size_t)qi * (PSH/4) + m] = outp;
        }
    }
    __syncthreads();

    // ---- P4: X = P @ V (fp16 mma m16n8k16), split-K over 8 warps ----
    float4 acc2[4];
#pragma unroll
    for (int nt = 0; nt < 4; nt++) acc2[nt] = make_float4(0.f, 0.f, 0.f, 0.f);

    for (int kt = 0; kt < 8; kt++) {
        if (kt < 7) {
            const int k0n = (kt + 1) * KTW;
#pragma unroll
            for (int i = 0; i < 8; i++) {
                int idx = t + 256 * i, kk = idx >> 3, j = idx & 7;
                st[i] = *(const float4*)&vsrc[(size_t)(k0n + kk) * C_ + j * 4];
            }
        }
        const int klo = wid * 32;
#pragma unroll
        for (int kc = 0; kc < 2; kc++) {
            const int kb = kt * KTW + klo + 16 * kc;    // absolute key base (even)
            const int kl = klo + 16 * kc;               // tile-local key base
            uint32_t a0 = probs_32[(size_t) g      * PSH32 + kb/2 + tq];
            uint32_t a1 = probs_32[(size_t)(g + 8) * PSH32 + kb/2 + tq];
            uint32_t a2 = probs_32[(size_t) g      * PSH32 + kb/2 + tq + 4];
            uint32_t a3 = probs_32[(size_t)(g + 8) * PSH32 + kb/2 + tq + 4];
#pragma unroll
            for (int nt = 0; nt < 4; nt++) {
                uint32_t b0 = vsm32[(8*nt + g) * (VTS/2) + kl/2 + tq];
                uint32_t b1 = vsm32[(8*nt + g) * (VTS/2) + kl/2 + tq + 4];
                mma16h(acc2[nt], a0, a1, a2, a3, b0, b1);
            }
        }
        __syncthreads();
        if (kt < 7) {
#pragma unroll
            for (int i = 0; i < 8; i++) {
                int idx = t + 256 * i, kk = idx >> 3, j = idx & 7;
                vsmh[(4*j + 0) * VTS + kk] = __float2half(st[i].x);
                vsmh[(4*j + 1) * VTS + kk] = __float2half(st[i].y);
                vsmh[(4*j + 2) * VTS + kk] = __float2half(st[i].z);
                vsmh[(4*j + 3) * VTS + kk] = __float2half(st[i].w);
            }
            __syncthreads();
        }
    }
    // stage per-warp X and reduce across 8 warps
    __syncthreads();   // vsmh reads done; reuse kvf region for X staging
#pragma unroll
    for (int nt = 0; nt < 4; nt++) {
        int d = 8 * nt + 2 * tq;
        *(float2*)&kvf[wid * XWARP +  g      * XSTR + d] = make_float2(acc2[nt].x, acc2[nt].y);
        *(float2*)&kvf[wid * XWARP + (g + 8) * XSTR + d] = make_float2(acc2[nt].z, acc2[nt].w);
    }
    __syncthreads();
#pragma unroll
    for (int i = 0; i < 2; i++) {
        int idx = t + 256 * i;
        int r = idx >> 5, d = idx & 31;
        float s = 0.f;
#pragma unroll
        for (int w2 = 0; w2 < 8; w2++) s += kvf[w2 * XWARP + r * XSTR + d];
        g_x[((size_t)b * N_ + q0 + r) * C_ + h * D_ + d] = s;
    }
}

// ---------------------------------------------------------------------------
extern "C" void kernel_launch(void* const* d_in, const int* in_sizes, int n_in,
                              void* d_out, int out_size) {
    (void)in_sizes; (void)n_in; (void)out_size;
    const float* query = (const float*)d_in[0];
    const float* mask  = (const float*)d_in[1];
    const float* Wq    = (const float*)d_in[2];
    const float* bq    = (const float*)d_in[3];
    const float* Wk    = (const float*)d_in[4];
    const float* bk    = (const float*)d_in[5];
    const float* Wv    = (const float*)d_in[6];
    const float* bv    = (const float*)d_in[7];
    const float* Wo    = (const float*)d_in[8];
    const float* bo    = (const float*)d_in[9];

    float* out      = (float*)d_out;
    float* attn_out = out + (size_t)B_ * N_ * C_;

    void* p;
    cudaGetSymbolAddress(&p, g_q);   float* gq = (float*)p;
    cudaGetSymbolAddress(&p, g_k);   float* gk = (float*)p;
    cudaGetSymbolAddress(&p, g_v);   float* gv = (float*)p;
    cudaGetSymbolAddress(&p, g_x);   float* gx = (float*)p;

    cudaFuncSetAttribute(attn_k, cudaFuncAttributeMaxDynamicSharedMemorySize, SM_BYTES);

    dim3 gg(4, 128);
    gemm_qkv<<<gg, 256>>>(query, Wq, bq, gq, Wk, bk, gk, Wv, bv, gv);

    cmax_init<<<(B_ * N_ + 255) / 256, 256>>>();
    cmax_k<<<dim3(8, 8, 4), 256>>>(mask);
    mt_k<<<dim3(N_ / 64, N_ / 64, B_), 256>>>(mask);

    attn_k<<<dim3(N_ / 16, H_, B_), 256, SM_BYTES>>>(attn_out);

    gemm_o<<<gg, 256>>>(gx, Wo, bo, query, out);
}

// round 14
// speedup vs baseline: 1.3163x; 1.3163x over previous
#include <cuda_runtime.h>
#include <cuda_fp16.h>
#include <cstdint>

// ---------------------------------------------------------------------------
// MaskMultiheadAttention  (B=4, N=2048, C=256, H=8, Dh=32)
// out = (query + proj_o(attn_masked @ V), softmax(QK^T*scale))
// d_out layout: [out_query (B*N*C floats)] [attn_vis (B*H*N*N floats)]
// Attention inner GEMMs via mma.sync tf32; K/V tiles in natural layout.
// ---------------------------------------------------------------------------

constexpr int B_ = 4, N_ = 2048, C_ = 256, H_ = 8, D_ = 32;
constexpr float SCALE_L2 = 0.17677669529663687f * 1.4426950408889634f;

__device__ float  g_q [B_ * N_ * C_];
__device__ float  g_k [B_ * N_ * C_];
__device__ float  g_v [B_ * N_ * C_];
__device__ float  g_x [B_ * N_ * C_];
__device__ __half g_mt[(size_t)B_ * N_ * N_];   // mask^T/colmax (fp16)
__device__ int    g_cmax[B_ * N_];

#define DEV_INLINE __device__ __forceinline__
typedef unsigned long long ull;

DEV_INLINE ull pk2(float lo, float hi) {
    ull r; asm("mov.b64 %0, {%1, %2};" : "=l"(r) : "f"(lo), "f"(hi)); return r;
}
DEV_INLINE float2 upk2(ull v) {
    float2 f; asm("mov.b64 {%0, %1}, %2;" : "=f"(f.x), "=f"(f.y) : "l"(v)); return f;
}
DEV_INLINE ull ffma2(ull a, ull b, ull c) {
    ull d; asm("fma.rn.f32x2 %0, %1, %2, %3;" : "=l"(d) : "l"(a), "l"(b), "l"(c)); return d;
}
DEV_INLINE float ex2f(float x) {
    float y; asm("ex2.approx.ftz.f32 %0, %1;" : "=f"(y) : "f"(x)); return y;
}
DEV_INLINE uint32_t fb(float x) { return __float_as_uint(x); }

// m16n8k8 tf32 MMA, row.col. Per-lane (g=lane>>2, tq=lane&3):
//  A: a0=(g,tq) a1=(g+8,tq) a2=(g,tq+4) a3=(g+8,tq+4)
//  B: b0=(k=tq,n=g) b1=(k=tq+4,n=g)
//  D: d0=(g,2tq) d1=(g,2tq+1) d2=(g+8,2tq) d3=(g+8,2tq+1)
DEV_INLINE void mma8(float4& d, uint32_t a0, uint32_t a1, uint32_t a2, uint32_t a3,
                     uint32_t b0, uint32_t b1) {
    asm volatile("mma.sync.aligned.m16n8k8.row.col.f32.tf32.tf32.f32 "
                 "{%0,%1,%2,%3}, {%4,%5,%6,%7}, {%8,%9}, {%0,%1,%2,%3};"
                 : "+f"(d.x), "+f"(d.y), "+f"(d.z), "+f"(d.w)
                 : "r"(a0), "r"(a1), "r"(a2), "r"(a3), "r"(b0), "r"(b1));
}

// ---------------------------------------------------------------------------
// QKV GEMM (NT, fused 3 outputs) — FFMA2 (proven)
// ---------------------------------------------------------------------------
__global__ void __launch_bounds__(256) gemm_qkv(
    const float* __restrict__ A,
    const float* __restrict__ W0, const float* __restrict__ b0, float* __restrict__ o0,
    const float* __restrict__ W1, const float* __restrict__ b1, float* __restrict__ o1,
    const float* __restrict__ W2, const float* __restrict__ b2, float* __restrict__ o2) {
    __shared__ float As[2][16][64];
    __shared__ float Bs[2][3][16][64];
    const int t  = threadIdx.x;
    const int m0 = blockIdx.y * 64;
    const int n0 = blockIdx.x * 64;
    const int ty = t >> 4, tx = t & 15;
    const int lr = t >> 2;
    const int lk = (t & 3) * 4;

    const float4* Ap  = (const float4*)&A [(size_t)(m0 + lr) * C_ + lk];
    const float4* W0p = (const float4*)&W0[(size_t)(n0 + lr) * C_ + lk];
    const float4* W1p = (const float4*)&W1[(size_t)(n0 + lr) * C_ + lk];
    const float4* W2p = (const float4*)&W2[(size_t)(n0 + lr) * C_ + lk];

    float4 sa = Ap[0], s0 = W0p[0], s1 = W1p[0], s2 = W2p[0];
    {
        As[0][lk+0][lr]=sa.x; As[0][lk+1][lr]=sa.y; As[0][lk+2][lr]=sa.z; As[0][lk+3][lr]=sa.w;
        Bs[0][0][lk+0][lr]=s0.x; Bs[0][0][lk+1][lr]=s0.y; Bs[0][0][lk+2][lr]=s0.z; Bs[0][0][lk+3][lr]=s0.w;
        Bs[0][1][lk+0][lr]=s1.x; Bs[0][1][lk+1][lr]=s1.y; Bs[0][1][lk+2][lr]=s1.z; Bs[0][1][lk+3][lr]=s1.w;
        Bs[0][2][lk+0][lr]=s2.x; Bs[0][2][lk+1][lr]=s2.y; Bs[0][2][lk+2][lr]=s2.z; Bs[0][2][lk+3][lr]=s2.w;
    }
    __syncthreads();

    ull acc[3][4][2];
#pragma unroll
    for (int w = 0; w < 3; w++)
#pragma unroll
        for (int i = 0; i < 4; i++) { acc[w][i][0] = 0ull; acc[w][i][1] = 0ull; }

    for (int kt = 0; kt < 16; kt++) {
        const int cur = kt & 1;
        if (kt < 15) {
            sa = Ap[4*(kt+1)]; s0 = W0p[4*(kt+1)]; s1 = W1p[4*(kt+1)]; s2 = W2p[4*(kt+1)];
        }
#pragma unroll
        for (int kk = 0; kk < 16; kk++) {
            ull bv[3][2];
#pragma unroll
            for (int w = 0; w < 3; w++) {
                bv[w][0] = *(const ull*)&Bs[cur][w][kk][tx*4];
                bv[w][1] = *(const ull*)&Bs[cur][w][kk][tx*4+2];
            }
#pragma unroll
            for (int i = 0; i < 4; i++) {
                float a = As[cur][kk][ty*4+i];
                ull ad = pk2(a, a);
#pragma unroll
                for (int w = 0; w < 3; w++) {
                    acc[w][i][0] = ffma2(ad, bv[w][0], acc[w][i][0]);
                    acc[w][i][1] = ffma2(ad, bv[w][1], acc[w][i][1]);
                }
            }
        }
        if (kt < 15) {
            const int nb = cur ^ 1;
            As[nb][lk+0][lr]=sa.x; As[nb][lk+1][lr]=sa.y; As[nb][lk+2][lr]=sa.z; As[nb][lk+3][lr]=sa.w;
            Bs[nb][0][lk+0][lr]=s0.x; Bs[nb][0][lk+1][lr]=s0.y; Bs[nb][0][lk+2][lr]=s0.z; Bs[nb][0][lk+3][lr]=s0.w;
            Bs[nb][1][lk+0][lr]=s1.x; Bs[nb][1][lk+1][lr]=s1.y; Bs[nb][1][lk+2][lr]=s1.z; Bs[nb][1][lk+3][lr]=s1.w;
            Bs[nb][2][lk+0][lr]=s2.x; Bs[nb][2][lk+1][lr]=s2.y; Bs[nb][2][lk+2][lr]=s2.z; Bs[nb][2][lk+3][lr]=s2.w;
        }
        __syncthreads();
    }

    const float* bias[3] = {b0, b1, b2};
    float*       outp[3] = {o0, o1, o2};
#pragma unroll
    for (int w = 0; w < 3; w++)
#pragma unroll
        for (int i = 0; i < 4; i++) {
            int m = m0 + ty*4 + i;
#pragma unroll
            for (int p = 0; p < 2; p++) {
                int n = n0 + tx*4 + p*2;
                float2 v = upk2(acc[w][i][p]);
                v.x += bias[w][n]; v.y += bias[w][n+1];
                *(float2*)&outp[w][(size_t)m * C_ + n] = v;
            }
        }
}

// ---------------------------------------------------------------------------
// Output GEMM with bias + residual — FFMA2 (proven)
// ---------------------------------------------------------------------------
__global__ void __launch_bounds__(256) gemm_o(const float* __restrict__ A,
                                              const float* __restrict__ W,
                                              const float* __restrict__ bias,
                                              const float* __restrict__ res,
                                              float* __restrict__ out) {
    __shared__ float As[2][16][64];
    __shared__ float Bs[2][16][64];
    const int t  = threadIdx.x;
    const int m0 = blockIdx.y * 64;
    const int n0 = blockIdx.x * 64;
    const int ty = t >> 4, tx = t & 15;
    const int lr = t >> 2;
    const int lk = (t & 3) * 4;

    const float4* Ap = (const float4*)&A[(size_t)(m0 + lr) * C_ + lk];
    const float4* Wp = (const float4*)&W[(size_t)(n0 + lr) * C_ + lk];

    float4 sa = Ap[0], sw = Wp[0];
    As[0][lk+0][lr]=sa.x; As[0][lk+1][lr]=sa.y; As[0][lk+2][lr]=sa.z; As[0][lk+3][lr]=sa.w;
    Bs[0][lk+0][lr]=sw.x; Bs[0][lk+1][lr]=sw.y; Bs[0][lk+2][lr]=sw.z; Bs[0][lk+3][lr]=sw.w;
    __syncthreads();

    ull acc[4][2];
#pragma unroll
    for (int i = 0; i < 4; i++) { acc[i][0] = 0ull; acc[i][1] = 0ull; }

    for (int kt = 0; kt < 16; kt++) {
        const int cur = kt & 1;
        if (kt < 15) { sa = Ap[4*(kt+1)]; sw = Wp[4*(kt+1)]; }
#pragma unroll
        for (int kk = 0; kk < 16; kk++) {
            ull bv0 = *(const ull*)&Bs[cur][kk][tx*4];
            ull bv1 = *(const ull*)&Bs[cur][kk][tx*4+2];
#pragma unroll
            for (int i = 0; i < 4; i++) {
                float a = As[cur][kk][ty*4+i];
                ull ad = pk2(a, a);
                acc[i][0] = ffma2(ad, bv0, acc[i][0]);
                acc[i][1] = ffma2(ad, bv1, acc[i][1]);
            }
        }
        if (kt < 15) {
            const int nb = cur ^ 1;
            As[nb][lk+0][lr]=sa.x; As[nb][lk+1][lr]=sa.y; As[nb][lk+2][lr]=sa.z; As[nb][lk+3][lr]=sa.w;
            Bs[nb][lk+0][lr]=sw.x; Bs[nb][lk+1][lr]=sw.y; Bs[nb][lk+2][lr]=sw.z; Bs[nb][lk+3][lr]=sw.w;
        }
        __syncthreads();
    }
#pragma unroll
    for (int i = 0; i < 4; i++) {
        int m = m0 + ty*4 + i;
#pragma unroll
        for (int p = 0; p < 2; p++) {
            int n = n0 + tx*4 + p*2;
            float2 v = upk2(acc[i][p]);
            v.x += bias[n]   + res[(size_t)m * C_ + n];
            v.y += bias[n+1] + res[(size_t)m * C_ + n + 1];
            *(float2*)&out[(size_t)m * C_ + n] = v;
        }
    }
}

// ---------------------------------------------------------------------------
// mask: column max, then normalized transpose (fp16): g_mt[b][q][k]
// ---------------------------------------------------------------------------
__global__ void __launch_bounds__(256) cmax_init() {
    int i = blockIdx.x * 256 + threadIdx.x;
    if (i < B_ * N_) g_cmax[i] = 0;
}
__global__ void __launch_bounds__(256) cmax_k(const float* __restrict__ mask) {
    int q = blockIdx.x * 256 + threadIdx.x;
    int b = blockIdx.z;
    const float* p = mask + (size_t)b * N_ * N_ + (size_t)(blockIdx.y * 256) * N_ + q;
    float m = 0.f;
#pragma unroll 8
    for (int k = 0; k < 256; k++) m = fmaxf(m, p[(size_t)k * N_]);
    atomicMax(&g_cmax[b * N_ + q], __float_as_int(m));
}
__global__ void __launch_bounds__(256) mt_k(const float* __restrict__ mask) {
    __shared__ float tl[64][65];
    const int t  = threadIdx.x;
    const int k0 = blockIdx.x * 64, qq0 = blockIdx.y * 64, b = blockIdx.z;
#pragma unroll
    for (int i = 0; i < 16; i++) {
        int idx = t + 256 * i;
        int r = idx >> 6, c = idx & 63;
        tl[r][c] = mask[((size_t)(b * N_ + k0 + r)) * N_ + qq0 + c];
    }
    __syncthreads();
#pragma unroll
    for (int i = 0; i < 16; i++) {
        int idx = t + 256 * i;
        int r = idx >> 6, c = idx & 63;
        float ic = 1.0f / __int_as_float(g_cmax[b * N_ + qq0 + r]);
        g_mt[((size_t)(b * N_ + qq0 + r)) * N_ + k0 + c] = __float2half(tl[c][r] * ic);
    }
}

// ---------------------------------------------------------------------------
// fused attention: one CTA = (b, h, 16 q rows). 512 threads (16 warps).
// mma.sync tf32 for QK^T and PV; K/V staged in natural [tok][d] layout.
// ---------------------------------------------------------------------------
constexpr int PS    = 2052;              // probs row stride (floats)
constexpr int KTW   = 512;               // keys per tile
constexpr int KVS   = 36;                // K/V smem row stride
constexpr int QFS   = 36;                // q smem row stride
constexpr int XSTR  = 36;                // x staging row stride
constexpr int XWARP = 576;               // per-warp x staging (16*36)
constexpr int OFF_KV = 16 * PS;          // 32832
constexpr int KVSZ   = KTW * KVS;        // 18432
constexpr int OFF_QF = OFF_KV + KVSZ;    // 51264
constexpr int OFF_ST = OFF_QF + 16*QFS;  // 51840
constexpr int SM_FLOATS = OFF_ST + 16 + 256;  // invs16 + wpart256 = 52112
constexpr int SM_BYTES  = SM_FLOATS * 4;      // 208448 B

__global__ void __launch_bounds__(512, 1) attn_k(float* __restrict__ attn_out) {
    extern __shared__ float sm[];
    float* probs = sm;
    float* kvf   = sm + OFF_KV;
    float* qf    = sm + OFF_QF;
    float* invs  = sm + OFF_ST;         // [16]
    float* wpart = invs + 16;           // [16 warps][16 rows]

    const int t    = threadIdx.x;
    const int wid  = t >> 5, lane = t & 31;
    const int g    = lane >> 2, tq = lane & 3;
    const int q0   = blockIdx.x * 16;
    const int h    = blockIdx.y;
    const int b    = blockIdx.z;

    const float* qsrc = g_q + ((size_t)b * N_ + q0) * C_ + h * D_;
    const float* ksrc = g_k + (size_t)b * N_ * C_ + h * D_;
    const float* vsrc = g_v + (size_t)b * N_ * C_ + h * D_;

    // ---- q tile: q*scale, stride 36 ----
    {
        int qi = t >> 5, d = t & 31;
        qf[qi * QFS + d] = qsrc[(size_t)qi * C_ + d] * SCALE_L2;
    }

    float4 st[8];
    // prologue: K tile 0, coalesced (8 lanes per token row)
#pragma unroll
    for (int i = 0; i < 8; i++) {
        int idx = t + 512 * i, kk = idx >> 3, j = idx & 7;
        st[i] = *(const float4*)&ksrc[(size_t)kk * C_ + j * 4];
    }
    __syncthreads();   // qf visible
#pragma unroll
    for (int i = 0; i < 8; i++) {
        int idx = t + 512 * i, kk = idx >> 3, j = idx & 7;
        *(float4*)&kvf[kk * KVS + j * 4] = st[i];
    }
    __syncthreads();

    // ---- Q A-fragments (loop-invariant): 16 regs ----
    uint32_t qa[4][4];
#pragma unroll
    for (int kc = 0; kc < 4; kc++) {
        qa[kc][0] = fb(qf[ g      * QFS + 8*kc + tq]);
        qa[kc][1] = fb(qf[(g + 8) * QFS + 8*kc + tq]);
        qa[kc][2] = fb(qf[ g      * QFS + 8*kc + tq + 4]);
        qa[kc][3] = fb(qf[(g + 8) * QFS + 8*kc + tq + 4]);
    }

    // ---- P1: S = QK^T (mma), exp2 + rowsum in registers ----
    const int nb = wid * 32;            // this warp's keys within tile
    float rs_lo = 0.f, rs_hi = 0.f;
    for (int kt = 0; kt < 4; kt++) {
        if (kt < 3) {
            const int k0n = (kt + 1) * KTW;
#pragma unroll
            for (int i = 0; i < 8; i++) {
                int idx = t + 512 * i, kk = idx >> 3, j = idx & 7;
                st[i] = *(const float4*)&ksrc[(size_t)(k0n + kk) * C_ + j * 4];
            }
        }
        float4 acc[4];
#pragma unroll
        for (int nt = 0; nt < 4; nt++) acc[nt] = make_float4(0.f, 0.f, 0.f, 0.f);
#pragma unroll
        for (int kc = 0; kc < 4; kc++) {
#pragma unroll
            for (int nt = 0; nt < 4; nt++) {
                const int tok = nb + 8*nt + g;
                uint32_t b0 = fb(kvf[tok * KVS + 8*kc + tq]);
                uint32_t b1 = fb(kvf[tok * KVS + 8*kc + tq + 4]);
                mma8(acc[nt], qa[kc][0], qa[kc][1], qa[kc][2], qa[kc][3], b0, b1);
            }
        }
        const int k0 = kt * KTW;
#pragma unroll
        for (int nt = 0; nt < 4; nt++) {
            float e0 = ex2f(acc[nt].x), e1 = ex2f(acc[nt].y);
            float e2 = ex2f(acc[nt].z), e3 = ex2f(acc[nt].w);
            rs_lo += e0 + e1; rs_hi += e2 + e3;
            int col = k0 + nb + 8*nt + 2*tq;
            *(float2*)&probs[(size_t) g      * PS + col] = make_float2(e0, e1);
            *(float2*)&probs[(size_t)(g + 8) * PS + col] = make_float2(e2, e3);
        }
        __syncthreads();
        if (kt < 3) {
#pragma unroll
            for (int i = 0; i < 8; i++) {
                int idx = t + 512 * i, kk = idx >> 3, j = idx & 7;
                *(float4*)&kvf[kk * KVS + j * 4] = st[i];
            }
            __syncthreads();
        }
    }

    // rowsum: quad reduce then cross-warp combine
    rs_lo += __shfl_xor_sync(0xffffffffu, rs_lo, 1);
    rs_lo += __shfl_xor_sync(0xffffffffu, rs_lo, 2);
    rs_hi += __shfl_xor_sync(0xffffffffu, rs_hi, 1);
    rs_hi += __shfl_xor_sync(0xffffffffu, rs_hi, 2);
    if (tq == 0) {
        wpart[wid * 16 + g]     = rs_lo;
        wpart[wid * 16 + g + 8] = rs_hi;
    }
    // stage V tile 0 (latency hidden behind stats + P3)
#pragma unroll
    for (int i = 0; i < 8; i++) {
        int idx = t + 512 * i, kk = idx >> 3, j = idx & 7;
        st[i] = *(const float4*)&vsrc[(size_t)kk * C_ + j * 4];
    }
    __syncthreads();
    if (t < 16) {
        float s = 0.f;
#pragma unroll
        for (int w = 0; w < 16; w++) s += wpart[w * 16 + t];
        invs[t] = 1.0f / s;
    }
    __syncthreads();
    // store V tile 0 (kvf free after P1)
#pragma unroll
    for (int i = 0; i < 8; i++) {
        int idx = t + 512 * i, kk = idx >> 3, j = idx & 7;
        *(float4*)&kvf[kk * KVS + j * 4] = st[i];
    }

    // ---- P3 merged: vis = e*invs (streaming store) ; probs = vis * g_mt ----
    {
        float4* ao4 = (float4*)(attn_out + (((size_t)b * H_ + h) * N_ + q0) * N_);
        const uint2* mt2 = (const uint2*)(g_mt + ((size_t)b * N_ + q0) * N_);
        float4* p4 = (float4*)probs;
#pragma unroll 4
        for (int i = 0; i < 16; i++) {
            int idx = t + 512 * i;
            int qi = idx >> 9, m = idx & 511;
            float4 v = p4[(size_t)qi * (PS/4) + m];
            float s = invs[qi];
            v.x *= s; v.y *= s; v.z *= s; v.w *= s;
            __stcs(&ao4[(size_t)qi * 512 + m], v);
            uint2 mv = mt2[(size_t)qi * 512 + m];
            float2 m01 = __half22float2(*(__half2*)&mv.x);
            float2 m23 = __half22float2(*(__half2*)&mv.y);
            v.x *= m01.x; v.y *= m01.y; v.z *= m23.x; v.w *= m23.y;
            p4[(size_t)qi * (PS/4) + m] = v;
        }
    }
    __syncthreads();

    // ---- P4: X = P @ V (mma), split-K over 16 warps ----
    float4 acc2[4];
#pragma unroll
    for (int nt = 0; nt < 4; nt++) acc2[nt] = make_float4(0.f, 0.f, 0.f, 0.f);

    for (int kt = 0; kt < 4; kt++) {
        if (kt < 3) {
            const int k0n = (kt + 1) * KTW;
#pragma unroll
            for (int i = 0; i < 8; i++) {
                int idx = t + 512 * i, kk = idx >> 3, j = idx & 7;
                st[i] = *(const float4*)&vsrc[(size_t)(k0n + kk) * C_ + j * 4];
            }
        }
        const int klo = wid * 32, ka0 = kt * KTW + klo;
#pragma unroll
        for (int kc = 0; kc < 4; kc++) {
            const int kb = ka0 + kc * 8;
            uint32_t a0 = fb(probs[(size_t) g      * PS + kb + tq]);
            uint32_t a1 = fb(probs[(size_t)(g + 8) * PS + kb + tq]);
            uint32_t a2 = fb(probs[(size_t) g      * PS + kb + tq + 4]);
            uint32_t a3 = fb(probs[(size_t)(g + 8) * PS + kb + tq + 4]);
            const int kl = klo + kc * 8;
#pragma unroll
            for (int nt = 0; nt < 4; nt++) {
                uint32_t b0 = fb(kvf[(kl + tq)     * KVS + 8*nt + g]);
                uint32_t b1 = fb(kvf[(kl + tq + 4) * KVS + 8*nt + g]);
                mma8(acc2[nt], a0, a1, a2, a3, b0, b1);
            }
        }
        __syncthreads();
        if (kt < 3) {
#pragma unroll
            for (int i = 0; i < 8; i++) {
                int idx = t + 512 * i, kk = idx >> 3, j = idx & 7;
                *(float4*)&kvf[kk * KVS + j * 4] = st[i];
            }
            __syncthreads();
        }
    }
    // stage per-warp X and reduce across 16 warps
#pragma unroll
    for (int nt = 0; nt < 4; nt++) {
        int d = 8 * nt + 2 * tq;
        *(float2*)&kvf[wid * XWARP +  g      * XSTR + d] = make_float2(acc2[nt].x, acc2[nt].y);
        *(float2*)&kvf[wid * XWARP + (g + 8) * XSTR + d] = make_float2(acc2[nt].z, acc2[nt].w);
    }
    __syncthreads();
    {
        int r = t >> 5, d = t & 31;
        float s = 0.f;
#pragma unroll
        for (int w2 = 0; w2 < 16; w2++) s += kvf[w2 * XWARP + r * XSTR + d];
        g_x[((size_t)b * N_ + q0 + r) * C_ + h * D_ + d] = s;
    }
}

// ---------------------------------------------------------------------------
extern "C" void kernel_launch(void* const* d_in, const int* in_sizes, int n_in,
                              void* d_out, int out_size) {
    (void)in_sizes; (void)n_in; (void)out_size;
    const float* query = (const float*)d_in[0];
    const float* mask  = (const float*)d_in[1];
    const float* Wq    = (const float*)d_in[2];
    const float* bq    = (const float*)d_in[3];
    const float* Wk    = (const float*)d_in[4];
    const float* bk    = (const float*)d_in[5];
    const float* Wv    = (const float*)d_in[6];
    const float* bv    = (const float*)d_in[7];
    const float* Wo    = (const float*)d_in[8];
    const float* bo    = (const float*)d_in[9];

    float* out      = (float*)d_out;
    float* attn_out = out + (size_t)B_ * N_ * C_;

    void* p;
    cudaGetSymbolAddress(&p, g_q);   float* gq = (float*)p;
    cudaGetSymbolAddress(&p, g_k);   float* gk = (float*)p;
    cudaGetSymbolAddress(&p, g_v);   float* gv = (float*)p;
    cudaGetSymbolAddress(&p, g_x);   float* gx = (float*)p;

    cudaFuncSetAttribute(attn_k, cudaFuncAttributeMaxDynamicSharedMemorySize, SM_BYTES);

    dim3 gg(4, 128);
    gemm_qkv<<<gg, 256>>>(query, Wq, bq, gq, Wk, bk, gk, Wv, bv, gv);

    cmax_init<<<(B_ * N_ + 255) / 256, 256>>>();
    cmax_k<<<dim3(8, 8, 4), 256>>>(mask);
    mt_k<<<dim3(N_ / 64, N_ / 64, B_), 256>>>(mask);

    attn_k<<<dim3(N_ / 16, H_, B_), 512, SM_BYTES>>>(attn_out);

    gemm_o<<<gg, 256>>>(gx, Wo, bo, query, out);
}

// round 15
// speedup vs baseline: 1.6128x; 1.2253x over previous
#include <cuda_runtime.h>
#include <cuda_fp16.h>
#include <cstdint>

// ---------------------------------------------------------------------------
// MaskMultiheadAttention  (B=4, N=2048, C=256, H=8, Dh=32)
// out = (query + proj_o(attn_masked @ V), softmax(QK^T*scale))
// d_out layout: [out_query (B*N*C floats)] [attn_vis (B*H*N*N floats)]
// Attention: 32-q-row CTAs, probs fp16 in smem, mma.sync tf32 both passes.
// ---------------------------------------------------------------------------

constexpr int B_ = 4, N_ = 2048, C_ = 256, H_ = 8, D_ = 32;
constexpr float SCALE_L2 = 0.17677669529663687f * 1.4426950408889634f;

__device__ float  g_q [B_ * N_ * C_];
__device__ float  g_k [B_ * N_ * C_];
__device__ float  g_v [B_ * N_ * C_];
__device__ float  g_x [B_ * N_ * C_];
__device__ __half g_mt[(size_t)B_ * N_ * N_];   // mask^T/colmax (fp16)
__device__ int    g_cmax[B_ * N_];

#define DEV_INLINE __device__ __forceinline__
typedef unsigned long long ull;

DEV_INLINE ull pk2(float lo, float hi) {
    ull r; asm("mov.b64 %0, {%1, %2};" : "=l"(r) : "f"(lo), "f"(hi)); return r;
}
DEV_INLINE float2 upk2(ull v) {
    float2 f; asm("mov.b64 {%0, %1}, %2;" : "=f"(f.x), "=f"(f.y) : "l"(v)); return f;
}
DEV_INLINE ull ffma2(ull a, ull b, ull c) {
    ull d; asm("fma.rn.f32x2 %0, %1, %2, %3;" : "=l"(d) : "l"(a), "l"(b), "l"(c)); return d;
}
DEV_INLINE float ex2f(float x) {
    float y; asm("ex2.approx.ftz.f32 %0, %1;" : "=f"(y) : "f"(x)); return y;
}
DEV_INLINE uint32_t fb(float x) { return __float_as_uint(x); }

// m16n8k8 tf32 MMA, row.col. Per-lane (g=lane>>2, tq=lane&3):
//  A: a0=(g,tq) a1=(g+8,tq) a2=(g,tq+4) a3=(g+8,tq+4)
//  B: b0=(k=tq,n=g) b1=(k=tq+4,n=g)
//  D: d0=(g,2tq) d1=(g,2tq+1) d2=(g+8,2tq) d3=(g+8,2tq+1)
DEV_INLINE void mma8(float4& d, uint32_t a0, uint32_t a1, uint32_t a2, uint32_t a3,
                     uint32_t b0, uint32_t b1) {
    asm volatile("mma.sync.aligned.m16n8k8.row.col.f32.tf32.tf32.f32 "
                 "{%0,%1,%2,%3}, {%4,%5,%6,%7}, {%8,%9}, {%0,%1,%2,%3};"
                 : "+f"(d.x), "+f"(d.y), "+f"(d.z), "+f"(d.w)
                 : "r"(a0), "r"(a1), "r"(a2), "r"(a3), "r"(b0), "r"(b1));
}

// ---------------------------------------------------------------------------
// QKV GEMM (NT, fused 3 outputs) — FFMA2 (proven)
// ---------------------------------------------------------------------------
__global__ void __launch_bounds__(256) gemm_qkv(
    const float* __restrict__ A,
    const float* __restrict__ W0, const float* __restrict__ b0, float* __restrict__ o0,
    const float* __restrict__ W1, const float* __restrict__ b1, float* __restrict__ o1,
    const float* __restrict__ W2, const float* __restrict__ b2, float* __restrict__ o2) {
    __shared__ float As[2][16][64];
    __shared__ float Bs[2][3][16][64];
    const int t  = threadIdx.x;
    const int m0 = blockIdx.y * 64;
    const int n0 = blockIdx.x * 64;
    const int ty = t >> 4, tx = t & 15;
    const int lr = t >> 2;
    const int lk = (t & 3) * 4;

    const float4* Ap  = (const float4*)&A [(size_t)(m0 + lr) * C_ + lk];
    const float4* W0p = (const float4*)&W0[(size_t)(n0 + lr) * C_ + lk];
    const float4* W1p = (const float4*)&W1[(size_t)(n0 + lr) * C_ + lk];
    const float4* W2p = (const float4*)&W2[(size_t)(n0 + lr) * C_ + lk];

    float4 sa = Ap[0], s0 = W0p[0], s1 = W1p[0], s2 = W2p[0];
    {
        As[0][lk+0][lr]=sa.x; As[0][lk+1][lr]=sa.y; As[0][lk+2][lr]=sa.z; As[0][lk+3][lr]=sa.w;
        Bs[0][0][lk+0][lr]=s0.x; Bs[0][0][lk+1][lr]=s0.y; Bs[0][0][lk+2][lr]=s0.z; Bs[0][0][lk+3][lr]=s0.w;
        Bs[0][1][lk+0][lr]=s1.x; Bs[0][1][lk+1][lr]=s1.y; Bs[0][1][lk+2][lr]=s1.z; Bs[0][1][lk+3][lr]=s1.w;
        Bs[0][2][lk+0][lr]=s2.x; Bs[0][2][lk+1][lr]=s2.y; Bs[0][2][lk+2][lr]=s2.z; Bs[0][2][lk+3][lr]=s2.w;
    }
    __syncthreads();

    ull acc[3][4][2];
#pragma unroll
    for (int w = 0; w < 3; w++)
#pragma unroll
        for (int i = 0; i < 4; i++) { acc[w][i][0] = 0ull; acc[w][i][1] = 0ull; }

    for (int kt = 0; kt < 16; kt++) {
        const int cur = kt & 1;
        if (kt < 15) {
            sa = Ap[4*(kt+1)]; s0 = W0p[4*(kt+1)]; s1 = W1p[4*(kt+1)]; s2 = W2p[4*(kt+1)];
        }
#pragma unroll
        for (int kk = 0; kk < 16; kk++) {
            ull bv[3][2];
#pragma unroll
            for (int w = 0; w < 3; w++) {
                bv[w][0] = *(const ull*)&Bs[cur][w][kk][tx*4];
                bv[w][1] = *(const ull*)&Bs[cur][w][kk][tx*4+2];
            }
#pragma unroll
            for (int i = 0; i < 4; i++) {
                float a = As[cur][kk][ty*4+i];
                ull ad = pk2(a, a);
#pragma unroll
                for (int w = 0; w < 3; w++) {
                    acc[w][i][0] = ffma2(ad, bv[w][0], acc[w][i][0]);
                    acc[w][i][1] = ffma2(ad, bv[w][1], acc[w][i][1]);
                }
            }
        }
        if (kt < 15) {
            const int nb = cur ^ 1;
            As[nb][lk+0][lr]=sa.x; As[nb][lk+1][lr]=sa.y; As[nb][lk+2][lr]=sa.z; As[nb][lk+3][lr]=sa.w;
            Bs[nb][0][lk+0][lr]=s0.x; Bs[nb][0][lk+1][lr]=s0.y; Bs[nb][0][lk+2][lr]=s0.z; Bs[nb][0][lk+3][lr]=s0.w;
            Bs[nb][1][lk+0][lr]=s1.x; Bs[nb][1][lk+1][lr]=s1.y; Bs[nb][1][lk+2][lr]=s1.z; Bs[nb][1][lk+3][lr]=s1.w;
            Bs[nb][2][lk+0][lr]=s2.x; Bs[nb][2][lk+1][lr]=s2.y; Bs[nb][2][lk+2][lr]=s2.z; Bs[nb][2][lk+3][lr]=s2.w;
        }
        __syncthreads();
    }

    const float* bias[3] = {b0, b1, b2};
    float*       outp[3] = {o0, o1, o2};
#pragma unroll
    for (int w = 0; w < 3; w++)
#pragma unroll
        for (int i = 0; i < 4; i++) {
            int m = m0 + ty*4 + i;
#pragma unroll
            for (int p = 0; p < 2; p++) {
                int n = n0 + tx*4 + p*2;
                float2 v = upk2(acc[w][i][p]);
                v.x += bias[w][n]; v.y += bias[w][n+1];
                *(float2*)&outp[w][(size_t)m * C_ + n] = v;
            }
        }
}

// ---------------------------------------------------------------------------
// Output GEMM with bias + residual — FFMA2 (proven)
// ---------------------------------------------------------------------------
__global__ void __launch_bounds__(256) gemm_o(const float* __restrict__ A,
                                              const float* __restrict__ W,
                                              const float* __restrict__ bias,
                                              const float* __restrict__ res,
                                              float* __restrict__ out) {
    __shared__ float As[2][16][64];
    __shared__ float Bs[2][16][64];
    const int t  = threadIdx.x;
    const int m0 = blockIdx.y * 64;
    const int n0 = blockIdx.x * 64;
    const int ty = t >> 4, tx = t & 15;
    const int lr = t >> 2;
    const int lk = (t & 3) * 4;

    const float4* Ap = (const float4*)&A[(size_t)(m0 + lr) * C_ + lk];
    const float4* Wp = (const float4*)&W[(size_t)(n0 + lr) * C_ + lk];

    float4 sa = Ap[0], sw = Wp[0];
    As[0][lk+0][lr]=sa.x; As[0][lk+1][lr]=sa.y; As[0][lk+2][lr]=sa.z; As[0][lk+3][lr]=sa.w;
    Bs[0][lk+0][lr]=sw.x; Bs[0][lk+1][lr]=sw.y; Bs[0][lk+2][lr]=sw.z; Bs[0][lk+3][lr]=sw.w;
    __syncthreads();

    ull acc[4][2];
#pragma unroll
    for (int i = 0; i < 4; i++) { acc[i][0] = 0ull; acc[i][1] = 0ull; }

    for (int kt = 0; kt < 16; kt++) {
        const int cur = kt & 1;
        if (kt < 15) { sa = Ap[4*(kt+1)]; sw = Wp[4*(kt+1)]; }
#pragma unroll
        for (int kk = 0; kk < 16; kk++) {
            ull bv0 = *(const ull*)&Bs[cur][kk][tx*4];
            ull bv1 = *(const ull*)&Bs[cur][kk][tx*4+2];
#pragma unroll
            for (int i = 0; i < 4; i++) {
                float a = As[cur][kk][ty*4+i];
                ull ad = pk2(a, a);
                acc[i][0] = ffma2(ad, bv0, acc[i][0]);
                acc[i][1] = ffma2(ad, bv1, acc[i][1]);
            }
        }
        if (kt < 15) {
            const int nb = cur ^ 1;
            As[nb][lk+0][lr]=sa.x; As[nb][lk+1][lr]=sa.y; As[nb][lk+2][lr]=sa.z; As[nb][lk+3][lr]=sa.w;
            Bs[nb][lk+0][lr]=sw.x; Bs[nb][lk+1][lr]=sw.y; Bs[nb][lk+2][lr]=sw.z; Bs[nb][lk+3][lr]=sw.w;
        }
        __syncthreads();
    }
#pragma unroll
    for (int i = 0; i < 4; i++) {
        int m = m0 + ty*4 + i;
#pragma unroll
        for (int p = 0; p < 2; p++) {
            int n = n0 + tx*4 + p*2;
            float2 v = upk2(acc[i][p]);
            v.x += bias[n]   + res[(size_t)m * C_ + n];
            v.y += bias[n+1] + res[(size_t)m * C_ + n + 1];
            *(float2*)&out[(size_t)m * C_ + n] = v;
        }
    }
}

// ---------------------------------------------------------------------------
// mask: column max, then normalized transpose (fp16): g_mt[b][q][k]
// ---------------------------------------------------------------------------
__global__ void __launch_bounds__(256) cmax_init() {
    int i = blockIdx.x * 256 + threadIdx.x;
    if (i < B_ * N_) g_cmax[i] = 0;
}
__global__ void __launch_bounds__(256) cmax_k(const float* __restrict__ mask) {
    int q = blockIdx.x * 256 + threadIdx.x;
    int b = blockIdx.z;
    const float* p = mask + (size_t)b * N_ * N_ + (size_t)(blockIdx.y * 256) * N_ + q;
    float m = 0.f;
#pragma unroll 8
    for (int k = 0; k < 256; k++) m = fmaxf(m, p[(size_t)k * N_]);
    atomicMax(&g_cmax[b * N_ + q], __float_as_int(m));
}
__global__ void __launch_bounds__(256) mt_k(const float* __restrict__ mask) {
    __shared__ float tl[64][65];
    const int t  = threadIdx.x;
    const int k0 = blockIdx.x * 64, qq0 = blockIdx.y * 64, b = blockIdx.z;
#pragma unroll
    for (int i = 0; i < 16; i++) {
        int idx = t + 256 * i;
        int r = idx >> 6, c = idx & 63;
        tl[r][c] = mask[((size_t)(b * N_ + k0 + r)) * N_ + qq0 + c];
    }
    __syncthreads();
#pragma unroll
    for (int i = 0; i < 16; i++) {
        int idx = t + 256 * i;
        int r = idx >> 6, c = idx & 63;
        float ic = 1.0f / __int_as_float(g_cmax[b * N_ + qq0 + r]);
        g_mt[((size_t)(b * N_ + qq0 + r)) * N_ + k0 + c] = __float2half(tl[c][r] * ic);
    }
}

// ---------------------------------------------------------------------------
// fused attention: one CTA = (b, h, 32 q rows). 512 threads (16 warps).
// probs fp16 in smem; tf32 mma both passes; K/V natural [tok][d] layout.
// ---------------------------------------------------------------------------
constexpr int QT    = 32;                 // q rows per CTA
constexpr int PSH   = 2056;               // probs row stride (halves, 16B mult)
constexpr int KTW   = 512;                // keys per tile
constexpr int KVS   = 36;                 // K/V smem row stride (floats)
constexpr int QFS   = 36;                 // q smem row stride
constexpr int XSTR  = 36;                 // x staging row stride
constexpr int XWARP = QT * XSTR;          // per-warp x staging (1152)
constexpr int OFF_KV = QT * PSH / 2;      // probs floats = 32896
constexpr int KVSZ   = KTW * KVS;         // 18432 (== 16*XWARP... 16*1152=18432) ✓
constexpr int OFF_QF = OFF_KV + KVSZ;     // 51328
constexpr int OFF_ST = OFF_QF + QT*QFS;   // 52480
constexpr int SM_FLOATS = OFF_ST + 32 + 512;  // invs32 + wpart(16*32) = 53024
constexpr int SM_BYTES  = SM_FLOATS * 4;      // 212096 B

__global__ void __launch_bounds__(512, 1) attn_k(float* __restrict__ attn_out) {
    extern __shared__ float sm[];
    __half* probs_h = (__half*)sm;
    float*  kvf     = sm + OFF_KV;
    float*  qf      = sm + OFF_QF;
    float*  invs    = sm + OFF_ST;       // [32]
    float*  wpart   = invs + 32;         // [16 warps][32 rows]

    const int t    = threadIdx.x;
    const int wid  = t >> 5, lane = t & 31;
    const int g    = lane >> 2, tq = lane & 3;
    const int q0   = blockIdx.x * QT;
    const int h    = blockIdx.y;
    const int b    = blockIdx.z;

    const float* qsrc = g_q + ((size_t)b * N_ + q0) * C_ + h * D_;
    const float* ksrc = g_k + (size_t)b * N_ * C_ + h * D_;
    const float* vsrc = g_v + (size_t)b * N_ * C_ + h * D_;

    // ---- q tile: q*scale, stride 36 (32 rows) ----
#pragma unroll
    for (int i = 0; i < 2; i++) {
        int idx = t + 512 * i;
        int qi = idx >> 5, d = idx & 31;
        qf[qi * QFS + d] = qsrc[(size_t)qi * C_ + d] * SCALE_L2;
    }

    float4 st[8];
    // prologue: K tile 0, coalesced
#pragma unroll
    for (int i = 0; i < 8; i++) {
        int idx = t + 512 * i, kk = idx >> 3, j = idx & 7;
        st[i] = *(const float4*)&ksrc[(size_t)kk * C_ + j * 4];
    }
    __syncthreads();   // qf visible
#pragma unroll
    for (int i = 0; i < 8; i++) {
        int idx = t + 512 * i, kk = idx >> 3, j = idx & 7;
        *(float4*)&kvf[kk * KVS + j * 4] = st[i];
    }
    __syncthreads();

    // ---- Q A-fragments (loop-invariant): 2 m-tiles x 4 kc x 4 = 32 regs ----
    uint32_t qa[2][4][4];
#pragma unroll
    for (int mt = 0; mt < 2; mt++)
#pragma unroll
        for (int kc = 0; kc < 4; kc++) {
            int r0 = mt * 16 + g, r1 = mt * 16 + g + 8;
            qa[mt][kc][0] = fb(qf[r0 * QFS + 8*kc + tq]);
            qa[mt][kc][1] = fb(qf[r1 * QFS + 8*kc + tq]);
            qa[mt][kc][2] = fb(qf[r0 * QFS + 8*kc + tq + 4]);
            qa[mt][kc][3] = fb(qf[r1 * QFS + 8*kc + tq + 4]);
        }

    // ---- P1: S = QK^T (mma), exp2 + rowsum in regs, store e as fp16 ----
    const int nb = wid * 32;
    float rs[2][2] = {{0.f, 0.f}, {0.f, 0.f}};
    for (int kt = 0; kt < 4; kt++) {
        if (kt < 3) {
            const int k0n = (kt + 1) * KTW;
#pragma unroll
            for (int i = 0; i < 8; i++) {
                int idx = t + 512 * i, kk = idx >> 3, j = idx & 7;
                st[i] = *(const float4*)&ksrc[(size_t)(k0n + kk) * C_ + j * 4];
            }
        }
        float4 acc[2][4];
#pragma unroll
        for (int mt = 0; mt < 2; mt++)
#pragma unroll
            for (int nt = 0; nt < 4; nt++) acc[mt][nt] = make_float4(0.f, 0.f, 0.f, 0.f);
#pragma unroll
        for (int kc = 0; kc < 4; kc++) {
#pragma unroll
            for (int nt = 0; nt < 4; nt++) {
                const int tok = nb + 8*nt + g;
                uint32_t b0 = fb(kvf[tok * KVS + 8*kc + tq]);
                uint32_t b1 = fb(kvf[tok * KVS + 8*kc + tq + 4]);
                mma8(acc[0][nt], qa[0][kc][0], qa[0][kc][1], qa[0][kc][2], qa[0][kc][3], b0, b1);
                mma8(acc[1][nt], qa[1][kc][0], qa[1][kc][1], qa[1][kc][2], qa[1][kc][3], b0, b1);
            }
        }
        const int k0 = kt * KTW;
#pragma unroll
        for (int mt = 0; mt < 2; mt++)
#pragma unroll
            for (int nt = 0; nt < 4; nt++) {
                float e0 = ex2f(acc[mt][nt].x), e1 = ex2f(acc[mt][nt].y);
                float e2 = ex2f(acc[mt][nt].z), e3 = ex2f(acc[mt][nt].w);
                rs[mt][0] += e0 + e1; rs[mt][1] += e2 + e3;
                int col = k0 + nb + 8*nt + 2*tq;
                *(__half2*)&probs_h[(size_t)(mt*16 + g)     * PSH + col] = __floats2half2_rn(e0, e1);
                *(__half2*)&probs_h[(size_t)(mt*16 + g + 8) * PSH + col] = __floats2half2_rn(e2, e3);
            }
        __syncthreads();
        if (kt < 3) {
#pragma unroll
            for (int i = 0; i < 8; i++) {
                int idx = t + 512 * i, kk = idx >> 3, j = idx & 7;
                *(float4*)&kvf[kk * KVS + j * 4] = st[i];
            }
            __syncthreads();
        }
    }

    // rowsum: quad reduce then cross-warp combine
#pragma unroll
    for (int mt = 0; mt < 2; mt++) {
        rs[mt][0] += __shfl_xor_sync(0xffffffffu, rs[mt][0], 1);
        rs[mt][0] += __shfl_xor_sync(0xffffffffu, rs[mt][0], 2);
        rs[mt][1] += __shfl_xor_sync(0xffffffffu, rs[mt][1], 1);
        rs[mt][1] += __shfl_xor_sync(0xffffffffu, rs[mt][1], 2);
    }
    if (tq == 0) {
#pragma unroll
        for (int mt = 0; mt < 2; mt++) {
            wpart[wid * 32 + mt*16 + g]     = rs[mt][0];
            wpart[wid * 32 + mt*16 + g + 8] = rs[mt][1];
        }
    }
    // stage V tile 0 (latency hidden behind stats + P3)
#pragma unroll
    for (int i = 0; i < 8; i++) {
        int idx = t + 512 * i, kk = idx >> 3, j = idx & 7;
        st[i] = *(const float4*)&vsrc[(size_t)kk * C_ + j * 4];
    }
    __syncthreads();
    if (t < 32) {
        float s = 0.f;
#pragma unroll
        for (int w = 0; w < 16; w++) s += wpart[w * 32 + t];
        invs[t] = 1.0f / s;
    }
    __syncthreads();
    // store V tile 0 (kvf free after P1)
#pragma unroll
    for (int i = 0; i < 8; i++) {
        int idx = t + 512 * i, kk = idx >> 3, j = idx & 7;
        *(float4*)&kvf[kk * KVS + j * 4] = st[i];
    }

    // ---- P3 merged: vis = e*invs (fp32, streaming) ; probs = half(vis*g_mt) ----
    {
        float4* ao4 = (float4*)(attn_out + (((size_t)b * H_ + h) * N_ + q0) * N_);
        const uint2* mt2 = (const uint2*)(g_mt + ((size_t)b * N_ + q0) * N_);
        uint2* p2 = (uint2*)probs_h;
#pragma unroll 4
        for (int i = 0; i < 32; i++) {
            int idx = t + 512 * i;
            int qi = idx >> 9, m = idx & 511;          // 512 uint2 (4 halves) per row
            uint2 pv = p2[(size_t)qi * (PSH/4) + m];
            float2 f01 = __half22float2(*(__half2*)&pv.x);
            float2 f23 = __half22float2(*(__half2*)&pv.y);
            float s = invs[qi];
            float4 v = make_float4(f01.x * s, f01.y * s, f23.x * s, f23.y * s);
            __stcs(&ao4[(size_t)qi * 512 + m], v);
            uint2 mv = mt2[(size_t)qi * 512 + m];
            float2 m01 = __half22float2(*(__half2*)&mv.x);
            float2 m23 = __half22float2(*(__half2*)&mv.y);
            uint2 outp;
            *(__half2*)&outp.x = __floats2half2_rn(v.x * m01.x, v.y * m01.y);
            *(__half2*)&outp.y = __floats2half2_rn(v.z * m23.x, v.w * m23.y);
            p2[(size_t)qi * (PSH/4) + m] = outp;
        }
    }
    __syncthreads();

    // ---- P4: X = P @ V (tf32 mma; A from fp16 probs via cvt), split-K 16 warps ----
    float4 acc2[2][4];
#pragma unroll
    for (int mt = 0; mt < 2; mt++)
#pragma unroll
        for (int nt = 0; nt < 4; nt++) acc2[mt][nt] = make_float4(0.f, 0.f, 0.f, 0.f);

    for (int kt = 0; kt < 4; kt++) {
        if (kt < 3) {
            const int k0n = (kt + 1) * KTW;
#pragma unroll
            for (int i = 0; i < 8; i++) {
                int idx = t + 512 * i, kk = idx >> 3, j = idx & 7;
                st[i] = *(const float4*)&vsrc[(size_t)(k0n + kk) * C_ + j * 4];
            }
        }
        const int klo = wid * 32, ka0 = kt * KTW + klo;
#pragma unroll
        for (int kc = 0; kc < 4; kc++) {
            const int kb = ka0 + kc * 8;
            uint32_t pa[2][4];
#pragma unroll
            for (int mt = 0; mt < 2; mt++) {
                int r0 = mt*16 + g, r1 = mt*16 + g + 8;
                pa[mt][0] = fb(__half2float(probs_h[(size_t)r0 * PSH + kb + tq]));
                pa[mt][1] = fb(__half2float(probs_h[(size_t)r1 * PSH + kb + tq]));
                pa[mt][2] = fb(__half2float(probs_h[(size_t)r0 * PSH + kb + tq + 4]));
                pa[mt][3] = fb(__half2float(probs_h[(size_t)r1 * PSH + kb + tq + 4]));
            }
            const int kl = klo + kc * 8;
#pragma unroll
            for (int nt = 0; nt < 4; nt++) {
                uint32_t b0 = fb(kvf[(kl + tq)     * KVS + 8*nt + g]);
                uint32_t b1 = fb(kvf[(kl + tq + 4) * KVS + 8*nt + g]);
                mma8(acc2[0][nt], pa[0][0], pa[0][1], pa[0][2], pa[0][3], b0, b1);
                mma8(acc2[1][nt], pa[1][0], pa[1][1], pa[1][2], pa[1][3], b0, b1);
            }
        }
        __syncthreads();
        if (kt < 3) {
#pragma unroll
            for (int i = 0; i < 8; i++) {
                int idx = t + 512 * i, kk = idx >> 3, j = idx & 7;
                *(float4*)&kvf[kk * KVS + j * 4] = st[i];
            }
            __syncthreads();
        }
    }
    // stage per-warp X (32 rows x 32 d) and reduce across 16 warps
#pragma unroll
    for (int mt = 0; mt < 2; mt++)
#pragma unroll
        for (int nt = 0; nt < 4; nt++) {
            int d = 8 * nt + 2 * tq;
            *(float2*)&kvf[wid * XWARP + (mt*16 + g)     * XSTR + d] =
                make_float2(acc2[mt][nt].x, acc2[mt][nt].y);
            *(float2*)&kvf[wid * XWARP + (mt*16 + g + 8) * XSTR + d] =
                make_float2(acc2[mt][nt].z, acc2[mt][nt].w);
        }
    __syncthreads();
#pragma unroll
    for (int i = 0; i < 2; i++) {
        int idx = t + 512 * i;
        int r = idx >> 5, d = idx & 31;
        float s = 0.f;
#pragma unroll
        for (int w2 = 0; w2 < 16; w2++) s += kvf[w2 * XWARP + r * XSTR + d];
        g_x[((size_t)b * N_ + q0 + r) * C_ + h * D_ + d] = s;
    }
}

// ---------------------------------------------------------------------------
extern "C" void kernel_launch(void* const* d_in, const int* in_sizes, int n_in,
                              void* d_out, int out_size) {
    (void)in_sizes; (void)n_in; (void)out_size;
    const float* query = (const float*)d_in[0];
    const float* mask  = (const float*)d_in[1];
    const float* Wq    = (const float*)d_in[2];
    const float* bq    = (const float*)d_in[3];
    const float* Wk    = (const float*)d_in[4];
    const float* bk    = (const float*)d_in[5];
    const float* Wv    = (const float*)d_in[6];
    const float* bv    = (const float*)d_in[7];
    const float* Wo    = (const float*)d_in[8];
    const float* bo    = (const float*)d_in[9];

    float* out      = (float*)d_out;
    float* attn_out = out + (size_t)B_ * N_ * C_;

    void* p;
    cudaGetSymbolAddress(&p, g_q);   float* gq = (float*)p;
    cudaGetSymbolAddress(&p, g_k);   float* gk = (float*)p;
    cudaGetSymbolAddress(&p, g_v);   float* gv = (float*)p;
    cudaGetSymbolAddress(&p, g_x);   float* gx = (float*)p;

    cudaFuncSetAttribute(attn_k, cudaFuncAttributeMaxDynamicSharedMemorySize, SM_BYTES);

    dim3 gg(4, 128);
    gemm_qkv<<<gg, 256>>>(query, Wq, bq, gq, Wk, bk, gk, Wv, bv, gv);

    cmax_init<<<(B_ * N_ + 255) / 256, 256>>>();
    cmax_k<<<dim3(8, 8, 4), 256>>>(mask);
    mt_k<<<dim3(N_ / 64, N_ / 64, B_), 256>>>(mask);

    attn_k<<<dim3(N_ / QT, H_, B_), 512, SM_BYTES>>>(attn_out);

    gemm_o<<<gg, 256>>>(gx, Wo, bo, query, out);
}